// round 13
// baseline (speedup 1.0000x reference)
#include <cuda_runtime.h>
#include <cuda_fp16.h>
#include <cstdint>
#include <math.h>

// ---------------- problem constants ----------------
#define BATCH   4
#define WIDTH   512
#define LAYERS  6
#define HEADS   8
#define DH      64
#define TDYN    16
#define NBLKS   12
#define NFT     128
#define BLK     146
#define SEQ     1752
#define ROWS    (BATCH*SEQ)   // 7008
#define MTILES  55            // ceil(7008/128)

// ---------------- scratch (static device memory) ----------------
__device__ float  g_h   [ROWS * WIDTH];          // residual (fp32)
__device__ __half g_a   [ROWS * WIDTH];          // LN out / gathered rows (fp16)
__device__ float  g_qkv [ROWS * 3 * WIDTH];      // qkv (fp32, feeds attention)
__device__ __half g_attn[ROWS * WIDTH];          // attention out (fp16)
__device__ __half g_mid [ROWS * 4 * WIDTH];      // MLP mid (fp16)
// fp16 weights: qkv | wo | fc | proj | head
#define WQ_OFF  0
#define WO_OFF  4718592
#define WF_OFF  (WO_OFF + 1572864)
#define WP_OFF  (WF_OFF + 6291456)
#define WH_OFF  (WP_OFF + 6291456)
#define W_TOTAL (WH_OFF + 524288)
__device__ __half g_w[W_TOTAL];

// ---------------- small helpers ----------------
__device__ __forceinline__ uint32_t smem_u32(const void* p) {
    uint32_t a;
    asm("{ .reg .u64 t; cvta.to.shared.u64 t, %1; cvt.u32.u64 %0, t; }" : "=r"(a) : "l"(p));
    return a;
}
__device__ __forceinline__ void cp16(uint32_t dst, const void* src, int bytes) {
    asm volatile("cp.async.cg.shared.global [%0], [%1], 16, %2;" :: "r"(dst), "l"(src), "r"(bytes));
}
__device__ __forceinline__ float gelu_exact(float v) {
    return 0.5f * v * (1.0f + erff(v * 0.7071067811865475f));
}
__device__ __forceinline__ void mma_f16(float* c, const uint32_t* a, const uint32_t* b) {
    asm volatile(
        "mma.sync.aligned.m16n8k16.row.col.f32.f16.f16.f32 "
        "{%0,%1,%2,%3}, {%4,%5,%6,%7}, {%8,%9}, {%0,%1,%2,%3};"
        : "+f"(c[0]), "+f"(c[1]), "+f"(c[2]), "+f"(c[3])
        : "r"(a[0]), "r"(a[1]), "r"(a[2]), "r"(a[3]), "r"(b[0]), "r"(b[1]));
}
__device__ __forceinline__ void ldsm_x4(uint32_t& r0, uint32_t& r1, uint32_t& r2, uint32_t& r3,
                                        uint32_t addr) {
    asm volatile("ldmatrix.sync.aligned.m8n8.x4.shared.b16 {%0,%1,%2,%3}, [%4];"
        : "=r"(r0), "=r"(r1), "=r"(r2), "=r"(r3) : "r"(addr));
}

// ---------------- fp32 -> fp16 weight conversion (once per launch) ----------------
__global__ void k_tohalf(const float* __restrict__ s, __half* __restrict__ d, int n4) {
    int i = blockIdx.x * 256 + threadIdx.x;
    if (i < n4) {
        float4 v = ((const float4*)s)[i];
        __half2 h0 = __floats2half2_rn(v.x, v.y);
        __half2 h1 = __floats2half2_rn(v.z, v.w);
        uint2 u;
        u.x = *(uint32_t*)&h0; u.y = *(uint32_t*)&h1;
        ((uint2*)d)[i] = u;
    }
}

// ---------------- assemble ----------------
__global__ void k_assemble(const float* __restrict__ x, const float* __restrict__ f,
                           const float* __restrict__ delim, float* __restrict__ h) {
    int row = blockIdx.x;
    int b = row / SEQ, s = row % SEQ;
    int n = s / BLK,  r = s % BLK;
    const float* src;
    if (r < NFT)                      src = x + (((size_t)(b * NBLKS + n) * NFT + r) * WIDTH);
    else if (r == NFT || r == BLK-1)  src = delim;
    else                              src = f + (((size_t)b * (NBLKS*TDYN) + n * TDYN + (r - NFT - 1)) * WIDTH);
    int c = threadIdx.x * 4;
    float4 v = *(const float4*)(src + c);
#pragma unroll
    for (int u = 0; u < 2; u++) {
        int j = (c >> 1) + u;
        double den = exp((2.0 * j / 512.0) * 9.210340371976184);
        float arg = (float)s / (float)den;
        double sv, cv;
        sincos((double)arg, &sv, &cv);
        if (u == 0) { v.x += (float)sv; v.y += (float)cv; }
        else        { v.z += (float)sv; v.w += (float)cv; }
    }
    *(float4*)(h + (size_t)row * WIDTH + c) = v;
}

// ---------------- layernorm -> fp16 output (feeds GEMMs) ----------------
__global__ void k_ln(const float* __restrict__ x, __half* __restrict__ y,
                     const float* __restrict__ scale, const float* __restrict__ bias) {
    int row = blockIdx.x;
    const float* xr = x + (size_t)row * WIDTH;
    int c = threadIdx.x * 4;
    float4 v = *(const float4*)(xr + c);
    float s  = v.x + v.y + v.z + v.w;
    float ss = v.x*v.x + v.y*v.y + v.z*v.z + v.w*v.w;
    __shared__ float red[8];
#pragma unroll
    for (int off = 16; off; off >>= 1) {
        s  += __shfl_xor_sync(0xffffffffu, s,  off);
        ss += __shfl_xor_sync(0xffffffffu, ss, off);
    }
    int w = threadIdx.x >> 5, l = threadIdx.x & 31;
    if (l == 0) { red[w] = s; red[4 + w] = ss; }
    __syncthreads();
    s  = red[0] + red[1] + red[2] + red[3];
    ss = red[4] + red[5] + red[6] + red[7];
    float mu   = s * (1.0f / WIDTH);
    float var  = ss * (1.0f / WIDTH) - mu * mu;
    float rstd = rsqrtf(var + 1e-5f);
    float4 sc = *(const float4*)(scale + c);
    float4 bi = *(const float4*)(bias  + c);
    __half2 h0 = __floats2half2_rn((v.x - mu) * rstd * sc.x + bi.x,
                                   (v.y - mu) * rstd * sc.y + bi.y);
    __half2 h1 = __floats2half2_rn((v.z - mu) * rstd * sc.z + bi.z,
                                   (v.w - mu) * rstd * sc.w + bi.w);
    uint2 u; u.x = *(uint32_t*)&h0; u.y = *(uint32_t*)&h1;
    *(uint2*)(y + (size_t)row * WIDTH + c) = u;
}

// ---------------- fp16 mma.sync GEMM, 3-stage cp.async + ldmatrix ----------------
// C[m,n] = sum_k A[m,k]*W[n,k] (+epi). A,W fp16; accum fp32.
// EPI: 0 = bias+store f32, 1 = bias+gelu+store f16, 2 = bias+residual accum f32, 3 = store f32
#define GPAD 72                            // halfs per smem row (64 + 8 pad) -> 144B stride
#define GSTG (128 * GPAD)                  // halfs per operand per stage
#define GNST 3
#define GS_BYTES (GNST * 2 * GSTG * 2)     // 110592 bytes

template <int EPI>
__global__ void __launch_bounds__(256, 2)
k_mma(const __half* __restrict__ A, const __half* __restrict__ W,
      const float* __restrict__ bias, void* __restrict__ Cv,
      int M, int N, int K) {
    extern __shared__ __half sm[];
    __half* AsB = sm;                      // [GNST][128][GPAD]
    __half* BsB = sm + GNST * GSTG;
    int tid = threadIdx.x, lane = tid & 31, wid = tid >> 5;
    int bm = blockIdx.x * 128, bn = blockIdx.y * 128;
    int wm = (wid & 1) * 64, wn = (wid >> 1) * 32;
    int gq = lane >> 2, lq = lane & 3;

    float acc[4][4][4];
#pragma unroll
    for (int i = 0; i < 4; i++)
#pragma unroll
        for (int j = 0; j < 4; j++)
#pragma unroll
            for (int r = 0; r < 4; r++) acc[i][j][r] = 0.0f;

    int KT = K >> 6;                       // BK = 64

    // ldmatrix per-lane source layout: row = (lane&15), col-half = (lane>>4)*8
    int lrow = lane & 15, lcol = (lane >> 4) * 8;
    uint32_t aOff = (uint32_t)(((wm + lrow) * GPAD + lcol) * 2);   // byte offset within stage
    uint32_t bOff = (uint32_t)(((wn + lrow) * GPAD + lcol) * 2);
    uint32_t aBase0 = smem_u32(AsB), bBase0 = smem_u32(BsB);

    // cp.async loader: 4 chunks per operand per thread (128 rows x 64 halfs = 1024 x 16B)
    int ldrow[4], ldc8[4], ldAok[4];
    const __half* ldA[4];
    const __half* ldW[4];
#pragma unroll
    for (int q = 0; q < 4; q++) {
        int ch = tid + q * 256;
        ldrow[q] = ch >> 3; ldc8[q] = (ch & 7) << 3;
        ldA[q] = A + (size_t)(bm + ldrow[q]) * K + ldc8[q];
        ldW[q] = W + (size_t)(bn + ldrow[q]) * K + ldc8[q];
        ldAok[q] = (bm + ldrow[q]) < M ? 16 : 0;
    }

    auto load_stage = [&](int kt, int buf) {
        int k0 = kt << 6;
#pragma unroll
        for (int q = 0; q < 4; q++) {
            uint32_t da = smem_u32(AsB + buf * GSTG + ldrow[q] * GPAD + ldc8[q]);
            cp16(da, ldA[q] + k0, ldAok[q]);
            uint32_t db = smem_u32(BsB + buf * GSTG + ldrow[q] * GPAD + ldc8[q]);
            cp16(db, ldW[q] + k0, 16);
        }
        asm volatile("cp.async.commit_group;" ::: "memory");
    };

    load_stage(0, 0);
    if (KT > 1) load_stage(1, 1);
    else asm volatile("cp.async.commit_group;" ::: "memory");

    for (int kt = 0; kt < KT; kt++) {
        int buf = kt % GNST;
        asm volatile("cp.async.wait_group 1;" ::: "memory");
        __syncthreads();

        int nk = kt + 2;
        if (nk < KT) load_stage(nk, nk % GNST);
        else asm volatile("cp.async.commit_group;" ::: "memory");

        uint32_t aAddr = aBase0 + buf * (GSTG * 2) + aOff;
        uint32_t bAddr = bBase0 + buf * (GSTG * 2) + bOff;
#pragma unroll
        for (int ks = 0; ks < 4; ks++) {
            uint32_t a[4][4], b[4][2];
#pragma unroll
            for (int i = 0; i < 4; i++)
                ldsm_x4(a[i][0], a[i][1], a[i][2], a[i][3],
                        aAddr + i * (16 * GPAD * 2) + ks * 32);
#pragma unroll
            for (int jj = 0; jj < 2; jj++) {
                uint32_t q0, q1, q2, q3;
                ldsm_x4(q0, q1, q2, q3, bAddr + jj * (16 * GPAD * 2) + ks * 32);
                b[2*jj+0][0] = q0; b[2*jj+0][1] = q2;   // n rows 0-7 : k lo, k hi
                b[2*jj+1][0] = q1; b[2*jj+1][1] = q3;   // n rows 8-15
            }
#pragma unroll
            for (int i = 0; i < 4; i++)
#pragma unroll
                for (int j = 0; j < 4; j++)
                    mma_f16(acc[i][j], a[i], b[j]);
        }
    }

    // epilogue: c0,c1 at (row=gq, col=2lq,2lq+1); c2,c3 at row+8
    float bv[4][2];
#pragma unroll
    for (int j = 0; j < 4; j++) {
        if (EPI != 3) {
            const float* bp = bias + bn + wn + j * 8 + 2 * lq;
            bv[j][0] = bp[0]; bv[j][1] = bp[1];
        } else { bv[j][0] = 0.0f; bv[j][1] = 0.0f; }
    }
#pragma unroll
    for (int i = 0; i < 4; i++) {
#pragma unroll
        for (int half = 0; half < 2; half++) {
            int r = bm + wm + i * 16 + gq + half * 8;
            if (r < M) {
#pragma unroll
                for (int j = 0; j < 4; j++) {
                    float e0 = acc[i][j][half * 2 + 0] + bv[j][0];
                    float e1 = acc[i][j][half * 2 + 1] + bv[j][1];
                    int col = bn + wn + j * 8 + 2 * lq;
                    if (EPI == 1) {
                        __half* cp = (__half*)Cv + (size_t)r * N + col;
                        *(__half2*)cp = __floats2half2_rn(gelu_exact(e0), gelu_exact(e1));
                    } else {
                        float* cp = (float*)Cv + (size_t)r * N + col;
                        if (EPI == 2) {
                            float2 old = *(const float2*)cp;
                            e0 += old.x; e1 += old.y;
                        }
                        *(float2*)cp = make_float2(e0, e1);
                    }
                }
            }
        }
    }
}

// ---------------- attention: 4 lanes per query (16 dims each) ----------------
__global__ void __launch_bounds__(512)
k_attn(const float* __restrict__ qkv, __half* __restrict__ out) {
    int bi = blockIdx.x, head = blockIdx.y;
    int b = bi / NBLKS, i = bi % NBLKS;
    int base = i * BLK;
    int L = NFT + 17 * (i + 1) + (i > 0 ? 1 : 0);

    __shared__ int   kidx[336];
    __shared__ float Ks[64][64];
    __shared__ float Vs[64][64];

    int tid = threadIdx.x;
    int qi = tid >> 2, part = tid & 3;
    for (int t = tid; t < L; t += 512) {
        int v;
        if (t < NFT)                     v = base + t;
        else if (t < NFT + 17 * (i + 1)) { int u = t - NFT; v = (u / 17) * BLK + NFT + (u % 17); }
        else                             v = base - 1;
        kidx[t] = v;
    }

    const float* qp = qkv + ((size_t)(b * SEQ + base + qi)) * (3 * WIDTH) + head * DH + part * 16;
    float q[16];
#pragma unroll
    for (int u = 0; u < 16; u += 4) *(float4*)&q[u] = *(const float4*)(qp + u);

    float m = -1e30f, ssum = 0.0f, o[16];
#pragma unroll
    for (int u = 0; u < 16; u++) o[u] = 0.0f;
    __syncthreads();

    for (int k0 = 0; k0 < L; k0 += 64) {
        int cnt = min(64, L - k0);
        for (int t = tid; t < cnt * 16; t += 512) {
            int kk = t >> 4, d4 = (t & 15) * 4;
            int sk = kidx[k0 + kk];
            const float* kp = qkv + ((size_t)(b * SEQ + sk)) * (3 * WIDTH) + WIDTH + head * DH;
            *(float4*)&Ks[kk][d4] = *(const float4*)(kp + d4);
            *(float4*)&Vs[kk][d4] = *(const float4*)(kp + WIDTH + d4);
        }
        __syncthreads();
        for (int kk = 0; kk < cnt; kk++) {
            const float* kr = &Ks[kk][part * 16];
            float s = 0.0f;
#pragma unroll
            for (int u = 0; u < 16; u += 4) {
                float4 kv = *(const float4*)(kr + u);
                s = fmaf(q[u+0], kv.x, s); s = fmaf(q[u+1], kv.y, s);
                s = fmaf(q[u+2], kv.z, s); s = fmaf(q[u+3], kv.w, s);
            }
            s += __shfl_xor_sync(0xffffffffu, s, 1);
            s += __shfl_xor_sync(0xffffffffu, s, 2);
            s *= 0.125f;
            float nm = fmaxf(m, s);
            float cc = exp2f((m - nm) * 1.4426950408889634f);
            float pp = exp2f((s - nm) * 1.4426950408889634f);
            ssum = ssum * cc + pp;
            const float* vr = &Vs[kk][part * 16];
#pragma unroll
            for (int u = 0; u < 16; u++) o[u] = fmaf(pp, vr[u], o[u] * cc);
            m = nm;
        }
        __syncthreads();
    }

    float inv = 1.0f / ssum;
    __half* op = out + ((size_t)(b * SEQ + base + qi)) * WIDTH + head * DH + part * 16;
#pragma unroll
    for (int u = 0; u < 16; u += 2)
        *(__half2*)(op + u) = __floats2half2_rn(o[u] * inv, o[u+1] * inv);
}

// ---------------- non-frame rows: o = v (to fp16) ----------------
__global__ void k_copyv(const float* __restrict__ qkv, __half* __restrict__ out) {
    int t = blockIdx.x;
    int b = t / (NBLKS * 18);
    int rem = t % (NBLKS * 18);
    int n = rem / 18;
    int r = NFT + rem % 18;
    int s = n * BLK + r;
    int c = threadIdx.x * 4;
    size_t row = (size_t)(b * SEQ + s);
    float4 v = *(const float4*)(qkv + row * (3 * WIDTH) + 2 * WIDTH + c);
    __half2 h0 = __floats2half2_rn(v.x, v.y);
    __half2 h1 = __floats2half2_rn(v.z, v.w);
    uint2 u; u.x = *(uint32_t*)&h0; u.y = *(uint32_t*)&h1;
    *(uint2*)(out + row * WIDTH + c) = u;
}

// ---------------- gather frame rows for head (to fp16) ----------------
__global__ void k_gather(const float* __restrict__ h, __half* __restrict__ g) {
    int m = blockIdx.x;
    int b = m / (NBLKS * NFT);
    int t = m % (NBLKS * NFT);
    int n = t / NFT, r = t % NFT;
    int s = n * BLK + r;
    int c = threadIdx.x * 4;
    float4 v = *(const float4*)(h + ((size_t)(b * SEQ + s)) * WIDTH + c);
    __half2 h0 = __floats2half2_rn(v.x, v.y);
    __half2 h1 = __floats2half2_rn(v.z, v.w);
    uint2 u; u.x = *(uint32_t*)&h0; u.y = *(uint32_t*)&h1;
    *(uint2*)(g + (size_t)m * WIDTH + c) = u;
}

// ---------------- launch ----------------
extern "C" void kernel_launch(void* const* d_in, const int* in_sizes, int n_in,
                              void* d_out, int out_size) {
    const float* x     = (const float*)d_in[0];
    const float* f     = (const float*)d_in[1];
    const float* delim = (const float*)d_in[2];
    const float* ln1s  = (const float*)d_in[3];
    const float* ln1b  = (const float*)d_in[4];
    const float* wqkv  = (const float*)d_in[5];
    const float* bqkv  = (const float*)d_in[6];
    const float* wo    = (const float*)d_in[7];
    const float* bo    = (const float*)d_in[8];
    const float* ln2s  = (const float*)d_in[9];
    const float* ln2b  = (const float*)d_in[10];
    const float* wfc   = (const float*)d_in[11];
    const float* bfc   = (const float*)d_in[12];
    const float* wpr   = (const float*)d_in[13];
    const float* bpr   = (const float*)d_in[14];
    const float* whead = (const float*)d_in[15];
    float* out = (float*)d_out;

    float *h, *qkv;
    __half *a, *attn, *mid, *w;
    cudaGetSymbolAddress((void**)&h,    g_h);
    cudaGetSymbolAddress((void**)&a,    g_a);
    cudaGetSymbolAddress((void**)&qkv,  g_qkv);
    cudaGetSymbolAddress((void**)&attn, g_attn);
    cudaGetSymbolAddress((void**)&mid,  g_mid);
    cudaGetSymbolAddress((void**)&w,    g_w);

    cudaFuncSetAttribute(k_mma<0>, cudaFuncAttributeMaxDynamicSharedMemorySize, GS_BYTES);
    cudaFuncSetAttribute(k_mma<1>, cudaFuncAttributeMaxDynamicSharedMemorySize, GS_BYTES);
    cudaFuncSetAttribute(k_mma<2>, cudaFuncAttributeMaxDynamicSharedMemorySize, GS_BYTES);
    cudaFuncSetAttribute(k_mma<3>, cudaFuncAttributeMaxDynamicSharedMemorySize, GS_BYTES);

    // convert weights to fp16 (round-to-nearest)
    k_tohalf<<<(4718592/4 + 255)/256, 256>>>(wqkv,  w + WQ_OFF, 4718592/4);
    k_tohalf<<<(1572864/4 + 255)/256, 256>>>(wo,    w + WO_OFF, 1572864/4);
    k_tohalf<<<(6291456/4 + 255)/256, 256>>>(wfc,   w + WF_OFF, 6291456/4);
    k_tohalf<<<(6291456/4 + 255)/256, 256>>>(wpr,   w + WP_OFF, 6291456/4);
    k_tohalf<<<(524288/4  + 255)/256, 256>>>(whead, w + WH_OFF, 524288/4);

    k_assemble<<<ROWS, 128>>>(x, f, delim, h);

    for (int l = 0; l < LAYERS; l++) {
        k_ln<<<ROWS, 128>>>(h, a, ln1s + l * WIDTH, ln1b + l * WIDTH);
        k_mma<0><<<dim3(MTILES, 12), 256, GS_BYTES>>>(
            a, w + WQ_OFF + (size_t)l * 3*WIDTH*WIDTH, bqkv + (size_t)l * 3*WIDTH,
            qkv, ROWS, 3*WIDTH, WIDTH);
        k_attn <<<dim3(BATCH * NBLKS, HEADS), 512>>>(qkv, attn);
        k_copyv<<<BATCH * NBLKS * 18, 128>>>(qkv, attn);
        k_mma<2><<<dim3(MTILES, 4), 256, GS_BYTES>>>(
            attn, w + WO_OFF + (size_t)l * WIDTH*WIDTH, bo + (size_t)l * WIDTH,
            h, ROWS, WIDTH, WIDTH);
        k_ln<<<ROWS, 128>>>(h, a, ln2s + l * WIDTH, ln2b + l * WIDTH);
        k_mma<1><<<dim3(MTILES, 16), 256, GS_BYTES>>>(
            a, w + WF_OFF + (size_t)l * 4*WIDTH*WIDTH, bfc + (size_t)l * 4*WIDTH,
            mid, ROWS, 4*WIDTH, WIDTH);
        k_mma<2><<<dim3(MTILES, 4), 256, GS_BYTES>>>(
            mid, w + WP_OFF + (size_t)l * WIDTH*4*WIDTH, bpr + (size_t)l * WIDTH,
            h, ROWS, WIDTH, 4*WIDTH);
    }

    k_gather<<<BATCH * NBLKS * NFT, 128>>>(h, a);
    k_mma<3><<<dim3(48, 8), 256, GS_BYTES>>>(
        a, w + WH_OFF, nullptr, out, BATCH * NBLKS * NFT, 1024, WIDTH);
}

// round 14
// speedup vs baseline: 1.0028x; 1.0028x over previous
#include <cuda_runtime.h>
#include <cuda_fp16.h>
#include <cstdint>
#include <math.h>

// ---------------- problem constants ----------------
#define BATCH   4
#define WIDTH   512
#define LAYERS  6
#define HEADS   8
#define DH      64
#define TDYN    16
#define NBLKS   12
#define NFT     128
#define BLK     146
#define SEQ     1752
#define ROWS    (BATCH*SEQ)   // 7008
#define MTILES  55            // ceil(7008/128)

// ---------------- scratch (static device memory) ----------------
__device__ float  g_h   [ROWS * WIDTH];          // residual (fp32)
__device__ __half g_a   [ROWS * WIDTH];          // LN out / gathered rows (fp16)
__device__ float  g_qkv [ROWS * 3 * WIDTH];      // qkv (fp32, feeds attention)
__device__ __half g_attn[ROWS * WIDTH];          // attention out (fp16)
__device__ __half g_mid [ROWS * 4 * WIDTH];      // MLP mid (fp16)
// fp16 weights: qkv | wo | fc | proj | head
#define WQ_OFF  0
#define WO_OFF  4718592
#define WF_OFF  (WO_OFF + 1572864)
#define WP_OFF  (WF_OFF + 6291456)
#define WH_OFF  (WP_OFF + 6291456)
#define W_TOTAL (WH_OFF + 524288)
__device__ __half g_w[W_TOTAL];

// ---------------- small helpers ----------------
__device__ __forceinline__ uint32_t smem_u32(const void* p) {
    uint32_t a;
    asm("{ .reg .u64 t; cvta.to.shared.u64 t, %1; cvt.u32.u64 %0, t; }" : "=r"(a) : "l"(p));
    return a;
}
__device__ __forceinline__ void cp16(uint32_t dst, const void* src, int bytes) {
    asm volatile("cp.async.cg.shared.global [%0], [%1], 16, %2;" :: "r"(dst), "l"(src), "r"(bytes));
}
__device__ __forceinline__ float gelu_exact(float v) {
    return 0.5f * v * (1.0f + erff(v * 0.7071067811865475f));
}
__device__ __forceinline__ void mma_f16(float* c, const uint32_t* a, const uint32_t* b) {
    asm volatile(
        "mma.sync.aligned.m16n8k16.row.col.f32.f16.f16.f32 "
        "{%0,%1,%2,%3}, {%4,%5,%6,%7}, {%8,%9}, {%0,%1,%2,%3};"
        : "+f"(c[0]), "+f"(c[1]), "+f"(c[2]), "+f"(c[3])
        : "r"(a[0]), "r"(a[1]), "r"(a[2]), "r"(a[3]), "r"(b[0]), "r"(b[1]));
}
__device__ __forceinline__ void ldsm_x4(uint32_t& r0, uint32_t& r1, uint32_t& r2, uint32_t& r3,
                                        uint32_t addr) {
    asm volatile("ldmatrix.sync.aligned.m8n8.x4.shared.b16 {%0,%1,%2,%3}, [%4];"
        : "=r"(r0), "=r"(r1), "=r"(r2), "=r"(r3) : "r"(addr));
}

// ---------------- fp32 -> fp16 weight conversion (once per launch) ----------------
__global__ void k_tohalf(const float* __restrict__ s, __half* __restrict__ d, int n4) {
    int i = blockIdx.x * 256 + threadIdx.x;
    if (i < n4) {
        float4 v = ((const float4*)s)[i];
        __half2 h0 = __floats2half2_rn(v.x, v.y);
        __half2 h1 = __floats2half2_rn(v.z, v.w);
        uint2 u;
        u.x = *(uint32_t*)&h0; u.y = *(uint32_t*)&h1;
        ((uint2*)d)[i] = u;
    }
}

// ---------------- assemble ----------------
__global__ void k_assemble(const float* __restrict__ x, const float* __restrict__ f,
                           const float* __restrict__ delim, float* __restrict__ h) {
    int row = blockIdx.x;
    int b = row / SEQ, s = row % SEQ;
    int n = s / BLK,  r = s % BLK;
    const float* src;
    if (r < NFT)                      src = x + (((size_t)(b * NBLKS + n) * NFT + r) * WIDTH);
    else if (r == NFT || r == BLK-1)  src = delim;
    else                              src = f + (((size_t)b * (NBLKS*TDYN) + n * TDYN + (r - NFT - 1)) * WIDTH);
    int c = threadIdx.x * 4;
    float4 v = *(const float4*)(src + c);
#pragma unroll
    for (int u = 0; u < 2; u++) {
        int j = (c >> 1) + u;
        double den = exp((2.0 * j / 512.0) * 9.210340371976184);
        float arg = (float)s / (float)den;
        double sv, cv;
        sincos((double)arg, &sv, &cv);
        if (u == 0) { v.x += (float)sv; v.y += (float)cv; }
        else        { v.z += (float)sv; v.w += (float)cv; }
    }
    *(float4*)(h + (size_t)row * WIDTH + c) = v;
}

// ---------------- layernorm -> fp16 output (feeds GEMMs) ----------------
__global__ void k_ln(const float* __restrict__ x, __half* __restrict__ y,
                     const float* __restrict__ scale, const float* __restrict__ bias) {
    int row = blockIdx.x;
    const float* xr = x + (size_t)row * WIDTH;
    int c = threadIdx.x * 4;
    float4 v = *(const float4*)(xr + c);
    float s  = v.x + v.y + v.z + v.w;
    float ss = v.x*v.x + v.y*v.y + v.z*v.z + v.w*v.w;
    __shared__ float red[8];
#pragma unroll
    for (int off = 16; off; off >>= 1) {
        s  += __shfl_xor_sync(0xffffffffu, s,  off);
        ss += __shfl_xor_sync(0xffffffffu, ss, off);
    }
    int w = threadIdx.x >> 5, l = threadIdx.x & 31;
    if (l == 0) { red[w] = s; red[4 + w] = ss; }
    __syncthreads();
    s  = red[0] + red[1] + red[2] + red[3];
    ss = red[4] + red[5] + red[6] + red[7];
    float mu   = s * (1.0f / WIDTH);
    float var  = ss * (1.0f / WIDTH) - mu * mu;
    float rstd = rsqrtf(var + 1e-5f);
    float4 sc = *(const float4*)(scale + c);
    float4 bi = *(const float4*)(bias  + c);
    __half2 h0 = __floats2half2_rn((v.x - mu) * rstd * sc.x + bi.x,
                                   (v.y - mu) * rstd * sc.y + bi.y);
    __half2 h1 = __floats2half2_rn((v.z - mu) * rstd * sc.z + bi.z,
                                   (v.w - mu) * rstd * sc.w + bi.w);
    uint2 u; u.x = *(uint32_t*)&h0; u.y = *(uint32_t*)&h1;
    *(uint2*)(y + (size_t)row * WIDTH + c) = u;
}

// ---------------- fp16 mma.sync GEMM, 3-stage cp.async + ldmatrix ----------------
// C[m,n] = sum_k A[m,k]*W[n,k] (+epi). A,W fp16; accum fp32.
// EPI: 0 = bias+store f32, 1 = bias+gelu+store f16, 2 = bias+residual accum f32, 3 = store f32
#define GPAD 72                            // halfs per smem row (64 + 8 pad) -> 144B stride
#define GSTG (128 * GPAD)                  // halfs per operand per stage
#define GNST 3
#define GS_BYTES (GNST * 2 * GSTG * 2)     // 110592 bytes

template <int EPI>
__global__ void __launch_bounds__(256, 2)
k_mma(const __half* __restrict__ A, const __half* __restrict__ W,
      const float* __restrict__ bias, void* __restrict__ Cv,
      int M, int N, int K) {
    extern __shared__ __half sm[];
    __half* AsB = sm;                      // [GNST][128][GPAD]
    __half* BsB = sm + GNST * GSTG;
    int tid = threadIdx.x, lane = tid & 31, wid = tid >> 5;
    int bm = blockIdx.x * 128, bn = blockIdx.y * 128;
    int wm = (wid & 1) * 64, wn = (wid >> 1) * 32;
    int gq = lane >> 2, lq = lane & 3;

    float acc[4][4][4];
#pragma unroll
    for (int i = 0; i < 4; i++)
#pragma unroll
        for (int j = 0; j < 4; j++)
#pragma unroll
            for (int r = 0; r < 4; r++) acc[i][j][r] = 0.0f;

    int KT = K >> 6;                       // BK = 64

    // ldmatrix per-lane source layout: row = (lane&15), col-half = (lane>>4)*8
    int lrow = lane & 15, lcol = (lane >> 4) * 8;
    uint32_t aOff = (uint32_t)(((wm + lrow) * GPAD + lcol) * 2);   // byte offset within stage
    uint32_t bOff = (uint32_t)(((wn + lrow) * GPAD + lcol) * 2);
    uint32_t aBase0 = smem_u32(AsB), bBase0 = smem_u32(BsB);

    // cp.async loader: 4 chunks per operand per thread (128 rows x 64 halfs = 1024 x 16B)
    int ldrow[4], ldc8[4], ldAok[4];
    const __half* ldA[4];
    const __half* ldW[4];
#pragma unroll
    for (int q = 0; q < 4; q++) {
        int ch = tid + q * 256;
        ldrow[q] = ch >> 3; ldc8[q] = (ch & 7) << 3;
        ldA[q] = A + (size_t)(bm + ldrow[q]) * K + ldc8[q];
        ldW[q] = W + (size_t)(bn + ldrow[q]) * K + ldc8[q];
        ldAok[q] = (bm + ldrow[q]) < M ? 16 : 0;
    }

    auto load_stage = [&](int kt, int buf) {
        int k0 = kt << 6;
#pragma unroll
        for (int q = 0; q < 4; q++) {
            uint32_t da = smem_u32(AsB + buf * GSTG + ldrow[q] * GPAD + ldc8[q]);
            cp16(da, ldA[q] + k0, ldAok[q]);
            uint32_t db = smem_u32(BsB + buf * GSTG + ldrow[q] * GPAD + ldc8[q]);
            cp16(db, ldW[q] + k0, 16);
        }
        asm volatile("cp.async.commit_group;" ::: "memory");
    };

    load_stage(0, 0);
    if (KT > 1) load_stage(1, 1);
    else asm volatile("cp.async.commit_group;" ::: "memory");

    for (int kt = 0; kt < KT; kt++) {
        int buf = kt % GNST;
        asm volatile("cp.async.wait_group 1;" ::: "memory");
        __syncthreads();

        int nk = kt + 2;
        if (nk < KT) load_stage(nk, nk % GNST);
        else asm volatile("cp.async.commit_group;" ::: "memory");

        uint32_t aAddr = aBase0 + buf * (GSTG * 2) + aOff;
        uint32_t bAddr = bBase0 + buf * (GSTG * 2) + bOff;
#pragma unroll
        for (int ks = 0; ks < 4; ks++) {
            uint32_t a[4][4], b[4][2];
#pragma unroll
            for (int i = 0; i < 4; i++)
                ldsm_x4(a[i][0], a[i][1], a[i][2], a[i][3],
                        aAddr + i * (16 * GPAD * 2) + ks * 32);
#pragma unroll
            for (int jj = 0; jj < 2; jj++) {
                uint32_t q0, q1, q2, q3;
                ldsm_x4(q0, q1, q2, q3, bAddr + jj * (16 * GPAD * 2) + ks * 32);
                b[2*jj+0][0] = q0; b[2*jj+0][1] = q2;   // n rows 0-7 : k lo, k hi
                b[2*jj+1][0] = q1; b[2*jj+1][1] = q3;   // n rows 8-15
            }
#pragma unroll
            for (int i = 0; i < 4; i++)
#pragma unroll
                for (int j = 0; j < 4; j++)
                    mma_f16(acc[i][j], a[i], b[j]);
        }
    }

    // epilogue: c0,c1 at (row=gq, col=2lq,2lq+1); c2,c3 at row+8
    float bv[4][2];
#pragma unroll
    for (int j = 0; j < 4; j++) {
        if (EPI != 3) {
            const float* bp = bias + bn + wn + j * 8 + 2 * lq;
            bv[j][0] = bp[0]; bv[j][1] = bp[1];
        } else { bv[j][0] = 0.0f; bv[j][1] = 0.0f; }
    }
#pragma unroll
    for (int i = 0; i < 4; i++) {
#pragma unroll
        for (int half = 0; half < 2; half++) {
            int r = bm + wm + i * 16 + gq + half * 8;
            if (r < M) {
#pragma unroll
                for (int j = 0; j < 4; j++) {
                    float e0 = acc[i][j][half * 2 + 0] + bv[j][0];
                    float e1 = acc[i][j][half * 2 + 1] + bv[j][1];
                    int col = bn + wn + j * 8 + 2 * lq;
                    if (EPI == 1) {
                        __half* cp = (__half*)Cv + (size_t)r * N + col;
                        *(__half2*)cp = __floats2half2_rn(gelu_exact(e0), gelu_exact(e1));
                    } else {
                        float* cp = (float*)Cv + (size_t)r * N + col;
                        if (EPI == 2) {
                            float2 old = *(const float2*)cp;
                            e0 += old.x; e1 += old.y;
                        }
                        *(float2*)cp = make_float2(e0, e1);
                    }
                }
            }
        }
    }
}

// ---------------- attention: 4 lanes per query (16 dims each) ----------------
__global__ void __launch_bounds__(512)
k_attn(const float* __restrict__ qkv, __half* __restrict__ out) {
    int bi = blockIdx.x, head = blockIdx.y;
    int b = bi / NBLKS, i = bi % NBLKS;
    int base = i * BLK;
    int L = NFT + 17 * (i + 1) + (i > 0 ? 1 : 0);

    __shared__ int   kidx[336];
    __shared__ float Ks[64][64];
    __shared__ float Vs[64][64];

    int tid = threadIdx.x;
    int qi = tid >> 2, part = tid & 3;
    for (int t = tid; t < L; t += 512) {
        int v;
        if (t < NFT)                     v = base + t;
        else if (t < NFT + 17 * (i + 1)) { int u = t - NFT; v = (u / 17) * BLK + NFT + (u % 17); }
        else                             v = base - 1;
        kidx[t] = v;
    }

    const float* qp = qkv + ((size_t)(b * SEQ + base + qi)) * (3 * WIDTH) + head * DH + part * 16;
    float q[16];
#pragma unroll
    for (int u = 0; u < 16; u += 4) *(float4*)&q[u] = *(const float4*)(qp + u);

    float m = -1e30f, ssum = 0.0f, o[16];
#pragma unroll
    for (int u = 0; u < 16; u++) o[u] = 0.0f;
    __syncthreads();

    for (int k0 = 0; k0 < L; k0 += 64) {
        int cnt = min(64, L - k0);
        for (int t = tid; t < cnt * 16; t += 512) {
            int kk = t >> 4, d4 = (t & 15) * 4;
            int sk = kidx[k0 + kk];
            const float* kp = qkv + ((size_t)(b * SEQ + sk)) * (3 * WIDTH) + WIDTH + head * DH;
            *(float4*)&Ks[kk][d4] = *(const float4*)(kp + d4);
            *(float4*)&Vs[kk][d4] = *(const float4*)(kp + WIDTH + d4);
        }
        __syncthreads();
        for (int kk = 0; kk < cnt; kk++) {
            const float* kr = &Ks[kk][part * 16];
            float s = 0.0f;
#pragma unroll
            for (int u = 0; u < 16; u += 4) {
                float4 kv = *(const float4*)(kr + u);
                s = fmaf(q[u+0], kv.x, s); s = fmaf(q[u+1], kv.y, s);
                s = fmaf(q[u+2], kv.z, s); s = fmaf(q[u+3], kv.w, s);
            }
            s += __shfl_xor_sync(0xffffffffu, s, 1);
            s += __shfl_xor_sync(0xffffffffu, s, 2);
            s *= 0.125f;
            float nm = fmaxf(m, s);
            float cc = exp2f((m - nm) * 1.4426950408889634f);
            float pp = exp2f((s - nm) * 1.4426950408889634f);
            ssum = ssum * cc + pp;
            const float* vr = &Vs[kk][part * 16];
#pragma unroll
            for (int u = 0; u < 16; u++) o[u] = fmaf(pp, vr[u], o[u] * cc);
            m = nm;
        }
        __syncthreads();
    }

    float inv = 1.0f / ssum;
    __half* op = out + ((size_t)(b * SEQ + base + qi)) * WIDTH + head * DH + part * 16;
#pragma unroll
    for (int u = 0; u < 16; u += 2)
        *(__half2*)(op + u) = __floats2half2_rn(o[u] * inv, o[u+1] * inv);
}

// ---------------- non-frame rows: o = v (to fp16) ----------------
__global__ void k_copyv(const float* __restrict__ qkv, __half* __restrict__ out) {
    int t = blockIdx.x;
    int b = t / (NBLKS * 18);
    int rem = t % (NBLKS * 18);
    int n = rem / 18;
    int r = NFT + rem % 18;
    int s = n * BLK + r;
    int c = threadIdx.x * 4;
    size_t row = (size_t)(b * SEQ + s);
    float4 v = *(const float4*)(qkv + row * (3 * WIDTH) + 2 * WIDTH + c);
    __half2 h0 = __floats2half2_rn(v.x, v.y);
    __half2 h1 = __floats2half2_rn(v.z, v.w);
    uint2 u; u.x = *(uint32_t*)&h0; u.y = *(uint32_t*)&h1;
    *(uint2*)(out + row * WIDTH + c) = u;
}

// ---------------- gather frame rows for head (to fp16) ----------------
__global__ void k_gather(const float* __restrict__ h, __half* __restrict__ g) {
    int m = blockIdx.x;
    int b = m / (NBLKS * NFT);
    int t = m % (NBLKS * NFT);
    int n = t / NFT, r = t % NFT;
    int s = n * BLK + r;
    int c = threadIdx.x * 4;
    float4 v = *(const float4*)(h + ((size_t)(b * SEQ + s)) * WIDTH + c);
    __half2 h0 = __floats2half2_rn(v.x, v.y);
    __half2 h1 = __floats2half2_rn(v.z, v.w);
    uint2 u; u.x = *(uint32_t*)&h0; u.y = *(uint32_t*)&h1;
    *(uint2*)(g + (size_t)m * WIDTH + c) = u;
}

// ---------------- launch ----------------
extern "C" void kernel_launch(void* const* d_in, const int* in_sizes, int n_in,
                              void* d_out, int out_size) {
    const float* x     = (const float*)d_in[0];
    const float* f     = (const float*)d_in[1];
    const float* delim = (const float*)d_in[2];
    const float* ln1s  = (const float*)d_in[3];
    const float* ln1b  = (const float*)d_in[4];
    const float* wqkv  = (const float*)d_in[5];
    const float* bqkv  = (const float*)d_in[6];
    const float* wo    = (const float*)d_in[7];
    const float* bo    = (const float*)d_in[8];
    const float* ln2s  = (const float*)d_in[9];
    const float* ln2b  = (const float*)d_in[10];
    const float* wfc   = (const float*)d_in[11];
    const float* bfc   = (const float*)d_in[12];
    const float* wpr   = (const float*)d_in[13];
    const float* bpr   = (const float*)d_in[14];
    const float* whead = (const float*)d_in[15];
    float* out = (float*)d_out;

    float *h, *qkv;
    __half *a, *attn, *mid, *w;
    cudaGetSymbolAddress((void**)&h,    g_h);
    cudaGetSymbolAddress((void**)&a,    g_a);
    cudaGetSymbolAddress((void**)&qkv,  g_qkv);
    cudaGetSymbolAddress((void**)&attn, g_attn);
    cudaGetSymbolAddress((void**)&mid,  g_mid);
    cudaGetSymbolAddress((void**)&w,    g_w);

    cudaFuncSetAttribute(k_mma<0>, cudaFuncAttributeMaxDynamicSharedMemorySize, GS_BYTES);
    cudaFuncSetAttribute(k_mma<1>, cudaFuncAttributeMaxDynamicSharedMemorySize, GS_BYTES);
    cudaFuncSetAttribute(k_mma<2>, cudaFuncAttributeMaxDynamicSharedMemorySize, GS_BYTES);
    cudaFuncSetAttribute(k_mma<3>, cudaFuncAttributeMaxDynamicSharedMemorySize, GS_BYTES);

    // convert weights to fp16 (round-to-nearest)
    k_tohalf<<<(4718592/4 + 255)/256, 256>>>(wqkv,  w + WQ_OFF, 4718592/4);
    k_tohalf<<<(1572864/4 + 255)/256, 256>>>(wo,    w + WO_OFF, 1572864/4);
    k_tohalf<<<(6291456/4 + 255)/256, 256>>>(wfc,   w + WF_OFF, 6291456/4);
    k_tohalf<<<(6291456/4 + 255)/256, 256>>>(wpr,   w + WP_OFF, 6291456/4);
    k_tohalf<<<(524288/4  + 255)/256, 256>>>(whead, w + WH_OFF, 524288/4);

    k_assemble<<<ROWS, 128>>>(x, f, delim, h);

    for (int l = 0; l < LAYERS; l++) {
        k_ln<<<ROWS, 128>>>(h, a, ln1s + l * WIDTH, ln1b + l * WIDTH);
        k_mma<0><<<dim3(MTILES, 12), 256, GS_BYTES>>>(
            a, w + WQ_OFF + (size_t)l * 3*WIDTH*WIDTH, bqkv + (size_t)l * 3*WIDTH,
            qkv, ROWS, 3*WIDTH, WIDTH);
        k_attn <<<dim3(BATCH * NBLKS, HEADS), 512>>>(qkv, attn);
        k_copyv<<<BATCH * NBLKS * 18, 128>>>(qkv, attn);
        k_mma<2><<<dim3(MTILES, 4), 256, GS_BYTES>>>(
            attn, w + WO_OFF + (size_t)l * WIDTH*WIDTH, bo + (size_t)l * WIDTH,
            h, ROWS, WIDTH, WIDTH);
        k_ln<<<ROWS, 128>>>(h, a, ln2s + l * WIDTH, ln2b + l * WIDTH);
        k_mma<1><<<dim3(MTILES, 16), 256, GS_BYTES>>>(
            a, w + WF_OFF + (size_t)l * 4*WIDTH*WIDTH, bfc + (size_t)l * 4*WIDTH,
            mid, ROWS, 4*WIDTH, WIDTH);
        k_mma<2><<<dim3(MTILES, 4), 256, GS_BYTES>>>(
            mid, w + WP_OFF + (size_t)l * WIDTH*4*WIDTH, bpr + (size_t)l * WIDTH,
            h, ROWS, WIDTH, 4*WIDTH);
    }

    k_gather<<<BATCH * NBLKS * NFT, 128>>>(h, a);
    k_mma<3><<<dim3(48, 8), 256, GS_BYTES>>>(
        a, w + WH_OFF, nullptr, out, BATCH * NBLKS * NFT, 1024, WIDTH);
}

// round 15
// speedup vs baseline: 2.6101x; 2.6029x over previous
#include <cuda_runtime.h>
#include <cuda_fp16.h>
#include <cstdint>
#include <math.h>

// ---------------- problem constants ----------------
#define BATCH   4
#define WIDTH   512
#define LAYERS  6
#define HEADS   8
#define DH      64
#define TDYN    16
#define NBLKS   12
#define NFT     128
#define BLK     146
#define SEQ     1752
#define ROWS    (BATCH*SEQ)   // 7008
#define MTILES  55            // ceil(7008/128)
#define LOG2E   1.4426950408889634f

// ---------------- scratch (static device memory) ----------------
__device__ float  g_h   [ROWS * WIDTH];          // residual (fp32)
__device__ __half g_a   [ROWS * WIDTH];          // LN out / gathered rows (fp16)
__device__ __half g_qkv [ROWS * 3 * WIDTH];      // qkv (fp16)
__device__ __half g_attn[ROWS * WIDTH];          // attention out (fp16)
__device__ __half g_mid [ROWS * 4 * WIDTH];      // MLP mid (fp16)
// fp16 weights: qkv | wo | fc | proj | head
#define WQ_OFF  0
#define WO_OFF  4718592
#define WF_OFF  (WO_OFF + 1572864)
#define WP_OFF  (WF_OFF + 6291456)
#define WH_OFF  (WP_OFF + 6291456)
#define W_TOTAL (WH_OFF + 524288)
__device__ __half g_w[W_TOTAL];

// ---------------- small helpers ----------------
__device__ __forceinline__ uint32_t smem_u32(const void* p) {
    uint32_t a;
    asm("{ .reg .u64 t; cvta.to.shared.u64 t, %1; cvt.u32.u64 %0, t; }" : "=r"(a) : "l"(p));
    return a;
}
__device__ __forceinline__ void cp16(uint32_t dst, const void* src, int bytes) {
    asm volatile("cp.async.cg.shared.global [%0], [%1], 16, %2;" :: "r"(dst), "l"(src), "r"(bytes));
}
__device__ __forceinline__ float gelu_exact(float v) {
    return 0.5f * v * (1.0f + erff(v * 0.7071067811865475f));
}
__device__ __forceinline__ void mma_f16(float* c, const uint32_t* a, const uint32_t* b) {
    asm volatile(
        "mma.sync.aligned.m16n8k16.row.col.f32.f16.f16.f32 "
        "{%0,%1,%2,%3}, {%4,%5,%6,%7}, {%8,%9}, {%0,%1,%2,%3};"
        : "+f"(c[0]), "+f"(c[1]), "+f"(c[2]), "+f"(c[3])
        : "r"(a[0]), "r"(a[1]), "r"(a[2]), "r"(a[3]), "r"(b[0]), "r"(b[1]));
}
__device__ __forceinline__ void ldsm_x4(uint32_t& r0, uint32_t& r1, uint32_t& r2, uint32_t& r3,
                                        uint32_t addr) {
    asm volatile("ldmatrix.sync.aligned.m8n8.x4.shared.b16 {%0,%1,%2,%3}, [%4];"
        : "=r"(r0), "=r"(r1), "=r"(r2), "=r"(r3) : "r"(addr));
}
__device__ __forceinline__ void ldsm_x4_t(uint32_t& r0, uint32_t& r1, uint32_t& r2, uint32_t& r3,
                                          uint32_t addr) {
    asm volatile("ldmatrix.sync.aligned.m8n8.x4.trans.shared.b16 {%0,%1,%2,%3}, [%4];"
        : "=r"(r0), "=r"(r1), "=r"(r2), "=r"(r3) : "r"(addr));
}
__device__ __forceinline__ uint32_t h2bits(float a, float b) {
    __half2 h = __floats2half2_rn(a, b);
    return *(uint32_t*)&h;
}

// ---------------- fp32 -> fp16 weight conversion (single launch) ----------------
__global__ void k_tohalf_all(const float* __restrict__ s0, const float* __restrict__ s1,
                             const float* __restrict__ s2, const float* __restrict__ s3,
                             const float* __restrict__ s4, __half* __restrict__ d) {
    const int b0 = 1179648, b1 = b0 + 393216, b2 = b1 + 1572864,
              b3 = b2 + 1572864, b4 = b3 + 131072;
    int i = blockIdx.x * 256 + threadIdx.x;
    const float* s; int off; __half* dst;
    if      (i < b0) { s = s0; off = i;      dst = d + WQ_OFF; }
    else if (i < b1) { s = s1; off = i - b0; dst = d + WO_OFF; }
    else if (i < b2) { s = s2; off = i - b1; dst = d + WF_OFF; }
    else if (i < b3) { s = s3; off = i - b2; dst = d + WP_OFF; }
    else if (i < b4) { s = s4; off = i - b3; dst = d + WH_OFF; }
    else return;
    float4 v = ((const float4*)s)[off];
    uint2 u;
    u.x = h2bits(v.x, v.y); u.y = h2bits(v.z, v.w);
    ((uint2*)dst)[off] = u;
}

// ---------------- assemble ----------------
__global__ void k_assemble(const float* __restrict__ x, const float* __restrict__ f,
                           const float* __restrict__ delim, float* __restrict__ h) {
    int row = blockIdx.x;
    int b = row / SEQ, s = row % SEQ;
    int n = s / BLK,  r = s % BLK;
    const float* src;
    if (r < NFT)                      src = x + (((size_t)(b * NBLKS + n) * NFT + r) * WIDTH);
    else if (r == NFT || r == BLK-1)  src = delim;
    else                              src = f + (((size_t)b * (NBLKS*TDYN) + n * TDYN + (r - NFT - 1)) * WIDTH);
    int c = threadIdx.x * 4;
    float4 v = *(const float4*)(src + c);
#pragma unroll
    for (int u = 0; u < 2; u++) {
        int j = (c >> 1) + u;
        double den = exp((2.0 * j / 512.0) * 9.210340371976184);
        float arg = (float)s / (float)den;
        double sv, cv;
        sincos((double)arg, &sv, &cv);
        if (u == 0) { v.x += (float)sv; v.y += (float)cv; }
        else        { v.z += (float)sv; v.w += (float)cv; }
    }
    *(float4*)(h + (size_t)row * WIDTH + c) = v;
}

// ---------------- layernorm -> fp16 output (feeds GEMMs) ----------------
__global__ void k_ln(const float* __restrict__ x, __half* __restrict__ y,
                     const float* __restrict__ scale, const float* __restrict__ bias) {
    int row = blockIdx.x;
    const float* xr = x + (size_t)row * WIDTH;
    int c = threadIdx.x * 4;
    float4 v = *(const float4*)(xr + c);
    float s  = v.x + v.y + v.z + v.w;
    float ss = v.x*v.x + v.y*v.y + v.z*v.z + v.w*v.w;
    __shared__ float red[8];
#pragma unroll
    for (int off = 16; off; off >>= 1) {
        s  += __shfl_xor_sync(0xffffffffu, s,  off);
        ss += __shfl_xor_sync(0xffffffffu, ss, off);
    }
    int w = threadIdx.x >> 5, l = threadIdx.x & 31;
    if (l == 0) { red[w] = s; red[4 + w] = ss; }
    __syncthreads();
    s  = red[0] + red[1] + red[2] + red[3];
    ss = red[4] + red[5] + red[6] + red[7];
    float mu   = s * (1.0f / WIDTH);
    float var  = ss * (1.0f / WIDTH) - mu * mu;
    float rstd = rsqrtf(var + 1e-5f);
    float4 sc = *(const float4*)(scale + c);
    float4 bi = *(const float4*)(bias  + c);
    uint2 u;
    u.x = h2bits((v.x - mu) * rstd * sc.x + bi.x, (v.y - mu) * rstd * sc.y + bi.y);
    u.y = h2bits((v.z - mu) * rstd * sc.z + bi.z, (v.w - mu) * rstd * sc.w + bi.w);
    *(uint2*)(y + (size_t)row * WIDTH + c) = u;
}

// ---------------- fp16 mma.sync GEMM (R12 mainloop), 3-stage cp.async ----------------
// EPI: 0 bias+f32, 1 bias+gelu+f16, 2 bias+residual f32, 3 plain f32, 4 bias+f16
#define GPAD 72
#define GSTG (128 * GPAD)
#define GNST 3
#define GS_BYTES (GNST * 2 * GSTG * 2)     // 110592 bytes

template <int EPI>
__global__ void __launch_bounds__(256, 2)
k_mma(const __half* __restrict__ A, const __half* __restrict__ W,
      const float* __restrict__ bias, void* __restrict__ Cv,
      int M, int N, int K) {
    extern __shared__ __half sm[];
    __half* AsB = sm;
    __half* BsB = sm + GNST * GSTG;
    int tid = threadIdx.x, lane = tid & 31, wid = tid >> 5;
    int bm = blockIdx.x * 128, bn = blockIdx.y * 128;
    int wm = (wid & 1) * 64, wn = (wid >> 1) * 32;
    int gq = lane >> 2, lq = lane & 3;

    float acc[4][4][4];
#pragma unroll
    for (int i = 0; i < 4; i++)
#pragma unroll
        for (int j = 0; j < 4; j++)
#pragma unroll
            for (int r = 0; r < 4; r++) acc[i][j][r] = 0.0f;

    int KT = K >> 6;

    int ldrow[4], ldc8[4], ldAok[4];
    const __half* ldA[4];
    const __half* ldW[4];
#pragma unroll
    for (int q = 0; q < 4; q++) {
        int ch = tid + q * 256;
        ldrow[q] = ch >> 3; ldc8[q] = (ch & 7) << 3;
        ldA[q] = A + (size_t)(bm + ldrow[q]) * K + ldc8[q];
        ldW[q] = W + (size_t)(bn + ldrow[q]) * K + ldc8[q];
        ldAok[q] = (bm + ldrow[q]) < M ? 16 : 0;
    }

    auto load_stage = [&](int kt, int buf) {
        int k0 = kt << 6;
#pragma unroll
        for (int q = 0; q < 4; q++) {
            uint32_t da = smem_u32(AsB + buf * GSTG + ldrow[q] * GPAD + ldc8[q]);
            cp16(da, ldA[q] + k0, ldAok[q]);
            uint32_t db = smem_u32(BsB + buf * GSTG + ldrow[q] * GPAD + ldc8[q]);
            cp16(db, ldW[q] + k0, 16);
        }
        asm volatile("cp.async.commit_group;" ::: "memory");
    };

    load_stage(0, 0);
    if (KT > 1) load_stage(1, 1);
    else asm volatile("cp.async.commit_group;" ::: "memory");

    for (int kt = 0; kt < KT; kt++) {
        int buf = kt % GNST;
        asm volatile("cp.async.wait_group 1;" ::: "memory");
        __syncthreads();

        int nk = kt + 2;
        if (nk < KT) load_stage(nk, nk % GNST);
        else asm volatile("cp.async.commit_group;" ::: "memory");

        const __half* Ab = AsB + buf * GSTG;
        const __half* Bb = BsB + buf * GSTG;
#pragma unroll
        for (int ks = 0; ks < 4; ks++) {
            int c0 = ks * 16 + 2 * lq;
            uint32_t a[4][4], b[4][2];
#pragma unroll
            for (int i = 0; i < 4; i++) {
                const __half* p = Ab + (wm + i * 16 + gq) * GPAD;
                a[i][0] = *(const uint32_t*)(p + c0);
                a[i][1] = *(const uint32_t*)(p + 8 * GPAD + c0);
                a[i][2] = *(const uint32_t*)(p + c0 + 8);
                a[i][3] = *(const uint32_t*)(p + 8 * GPAD + c0 + 8);
            }
#pragma unroll
            for (int j = 0; j < 4; j++) {
                const __half* p = Bb + (wn + j * 8 + gq) * GPAD;
                b[j][0] = *(const uint32_t*)(p + c0);
                b[j][1] = *(const uint32_t*)(p + c0 + 8);
            }
#pragma unroll
            for (int i = 0; i < 4; i++)
#pragma unroll
                for (int j = 0; j < 4; j++)
                    mma_f16(acc[i][j], a[i], b[j]);
        }
    }

    float bv[4][2];
#pragma unroll
    for (int j = 0; j < 4; j++) {
        if (EPI != 3) {
            const float* bp = bias + bn + wn + j * 8 + 2 * lq;
            bv[j][0] = bp[0]; bv[j][1] = bp[1];
        } else { bv[j][0] = 0.0f; bv[j][1] = 0.0f; }
    }
#pragma unroll
    for (int i = 0; i < 4; i++) {
#pragma unroll
        for (int half = 0; half < 2; half++) {
            int r = bm + wm + i * 16 + gq + half * 8;
            if (r < M) {
#pragma unroll
                for (int j = 0; j < 4; j++) {
                    float e0 = acc[i][j][half * 2 + 0] + bv[j][0];
                    float e1 = acc[i][j][half * 2 + 1] + bv[j][1];
                    int col = bn + wn + j * 8 + 2 * lq;
                    if (EPI == 1) {
                        __half* cp = (__half*)Cv + (size_t)r * N + col;
                        *(__half2*)cp = __floats2half2_rn(gelu_exact(e0), gelu_exact(e1));
                    } else if (EPI == 4) {
                        __half* cp = (__half*)Cv + (size_t)r * N + col;
                        *(__half2*)cp = __floats2half2_rn(e0, e1);
                    } else {
                        float* cp = (float*)Cv + (size_t)r * N + col;
                        if (EPI == 2) {
                            float2 old = *(const float2*)cp;
                            e0 += old.x; e1 += old.y;
                        }
                        *(float2*)cp = make_float2(e0, e1);
                    }
                }
            }
        }
    }
}

// ---------------- flash attention with tensor cores ----------------
// grid (48, 8), 128 threads (4 warps, 32 q-rows each). Chunks of 64 gathered keys.
__global__ void __launch_bounds__(128)
k_fattn(const __half* __restrict__ qkv, __half* __restrict__ out) {
    int bi = blockIdx.x, head = blockIdx.y;
    int b = bi / NBLKS, i = bi % NBLKS;
    int base = i * BLK;
    int L = NFT + 17 * (i + 1) + (i > 0 ? 1 : 0);

    __shared__ __half Qs[128][72];
    __shared__ __half Ks[64][72];
    __shared__ __half Vs[64][72];
    __shared__ int kidx[336];

    int tid = threadIdx.x, lane = tid & 31, warp = tid >> 5;
    int gq = lane >> 2, lq = lane & 3;
    int lrow = lane & 15, lcolb = (lane >> 4) * 8;

    for (int t = tid; t < L; t += 128) {
        int v;
        if (t < NFT)                     v = base + t;
        else if (t < NFT + 17 * (i + 1)) { int u = t - NFT; v = (u / 17) * BLK + NFT + (u % 17); }
        else                             v = base - 1;
        kidx[t] = v;
    }
    {   // load Q tile (one row per thread, 128B)
        const uint4* src = (const uint4*)(qkv + ((size_t)(b * SEQ + base + tid)) * (3*WIDTH) + head * DH);
#pragma unroll
        for (int c = 0; c < 8; c++)
            *(uint4*)&Qs[tid][c * 8] = src[c];
    }
    __syncthreads();

    // persistent Q a-fragments: [mi][k-step][4]
    uint32_t qf[2][4][4];
#pragma unroll
    for (int mi = 0; mi < 2; mi++)
#pragma unroll
        for (int kk = 0; kk < 4; kk++)
            ldsm_x4(qf[mi][kk][0], qf[mi][kk][1], qf[mi][kk][2], qf[mi][kk][3],
                    smem_u32(&Qs[warp * 32 + mi * 16 + lrow][kk * 16 + lcolb]));

    float mrow[2][2], ssum[2][2], ao[2][8][4];
#pragma unroll
    for (int mi = 0; mi < 2; mi++)
#pragma unroll
        for (int rh = 0; rh < 2; rh++) { mrow[mi][rh] = -1e30f; ssum[mi][rh] = 0.0f; }
#pragma unroll
    for (int mi = 0; mi < 2; mi++)
#pragma unroll
        for (int dj = 0; dj < 8; dj++)
#pragma unroll
            for (int r = 0; r < 4; r++) ao[mi][dj][r] = 0.0f;

    for (int k0 = 0; k0 < L; k0 += 64) {
        int cnt = min(64, L - k0);
        __syncthreads();           // previous chunk fully consumed
        {   // gather K/V chunk: thread t -> row t/2, half (t&1)
            int r2 = tid >> 1, hh = (tid & 1) * 32;
            if (r2 < cnt) {
                size_t rbase = (size_t)(b * SEQ + kidx[k0 + r2]) * (3*WIDTH);
                const uint4* kp = (const uint4*)(qkv + rbase + WIDTH     + head * DH + hh);
                const uint4* vp = (const uint4*)(qkv + rbase + 2*WIDTH   + head * DH + hh);
#pragma unroll
                for (int c = 0; c < 4; c++) {
                    *(uint4*)&Ks[r2][hh + c * 8] = kp[c];
                    *(uint4*)&Vs[r2][hh + c * 8] = vp[c];
                }
            }
        }
        __syncthreads();

        // S = Q K^T  -> sc[mi][nj][4]
        float sc[2][8][4];
#pragma unroll
        for (int mi = 0; mi < 2; mi++)
#pragma unroll
            for (int nj = 0; nj < 8; nj++)
#pragma unroll
                for (int r = 0; r < 4; r++) sc[mi][nj][r] = 0.0f;
#pragma unroll
        for (int kg = 0; kg < 4; kg++) {
#pragma unroll
            for (int kk = 0; kk < 4; kk++) {
                uint32_t t0, t1, t2, t3;
                ldsm_x4(t0, t1, t2, t3, smem_u32(&Ks[kg * 16 + lrow][kk * 16 + lcolb]));
                uint32_t be[2] = {t0, t2}, bo[2] = {t1, t3};
                mma_f16(sc[0][2*kg],   qf[0][kk], be);
                mma_f16(sc[0][2*kg+1], qf[0][kk], bo);
                mma_f16(sc[1][2*kg],   qf[1][kk], be);
                mma_f16(sc[1][2*kg+1], qf[1][kk], bo);
            }
        }

        // online softmax (per row-group; shuffles amortized per chunk)
#pragma unroll
        for (int mi = 0; mi < 2; mi++)
#pragma unroll
        for (int rh = 0; rh < 2; rh++) {
            float mx = -1e30f;
#pragma unroll
            for (int nj = 0; nj < 8; nj++)
#pragma unroll
                for (int cc = 0; cc < 2; cc++) {
                    int col = nj * 8 + 2 * lq + cc;
                    float s = (col < cnt) ? sc[mi][nj][rh * 2 + cc] * 0.125f : -1e30f;
                    sc[mi][nj][rh * 2 + cc] = s;
                    mx = fmaxf(mx, s);
                }
            mx = fmaxf(mx, __shfl_xor_sync(0xffffffffu, mx, 1));
            mx = fmaxf(mx, __shfl_xor_sync(0xffffffffu, mx, 2));
            float nm = fmaxf(mrow[mi][rh], mx);
            float co = exp2f((mrow[mi][rh] - nm) * LOG2E);
            float ps = 0.0f;
#pragma unroll
            for (int nj = 0; nj < 8; nj++)
#pragma unroll
                for (int cc = 0; cc < 2; cc++) {
                    float p = exp2f((sc[mi][nj][rh * 2 + cc] - nm) * LOG2E);
                    sc[mi][nj][rh * 2 + cc] = p;
                    ps += p;
                }
            ps += __shfl_xor_sync(0xffffffffu, ps, 1);
            ps += __shfl_xor_sync(0xffffffffu, ps, 2);
            ssum[mi][rh] = ssum[mi][rh] * co + ps;
            mrow[mi][rh] = nm;
#pragma unroll
            for (int dj = 0; dj < 8; dj++) {
                ao[mi][dj][rh * 2 + 0] *= co;
                ao[mi][dj][rh * 2 + 1] *= co;
            }
        }

        // O += P V  (P -> fp16 a-frags per 16-key tile; V via ldmatrix.trans)
#pragma unroll
        for (int kt = 0; kt < 4; kt++) {
            uint32_t ph[2][4];
#pragma unroll
            for (int mi = 0; mi < 2; mi++) {
                ph[mi][0] = h2bits(sc[mi][2*kt][0],   sc[mi][2*kt][1]);
                ph[mi][1] = h2bits(sc[mi][2*kt][2],   sc[mi][2*kt][3]);
                ph[mi][2] = h2bits(sc[mi][2*kt+1][0], sc[mi][2*kt+1][1]);
                ph[mi][3] = h2bits(sc[mi][2*kt+1][2], sc[mi][2*kt+1][3]);
            }
#pragma unroll
            for (int dh2 = 0; dh2 < 4; dh2++) {
                uint32_t r0, r1, r2, r3;
                ldsm_x4_t(r0, r1, r2, r3, smem_u32(&Vs[kt * 16 + lrow][dh2 * 16 + lcolb]));
                uint32_t be[2] = {r0, r1}, bo[2] = {r2, r3};
                mma_f16(ao[0][2*dh2],   ph[0], be);
                mma_f16(ao[0][2*dh2+1], ph[0], bo);
                mma_f16(ao[1][2*dh2],   ph[1], be);
                mma_f16(ao[1][2*dh2+1], ph[1], bo);
            }
        }
    }

    // normalize + store fp16
#pragma unroll
    for (int mi = 0; mi < 2; mi++)
#pragma unroll
    for (int rh = 0; rh < 2; rh++) {
        float inv = 1.0f / ssum[mi][rh];
        int r = base + warp * 32 + mi * 16 + gq + rh * 8;
        __half* op = out + ((size_t)(b * SEQ + r)) * WIDTH + head * DH + 2 * lq;
#pragma unroll
        for (int dj = 0; dj < 8; dj++)
            *(__half2*)(op + dj * 8) =
                __floats2half2_rn(ao[mi][dj][rh * 2] * inv, ao[mi][dj][rh * 2 + 1] * inv);
    }
}

// ---------------- non-frame rows: o = v (fp16 copy) ----------------
__global__ void k_copyv(const __half* __restrict__ qkv, __half* __restrict__ out) {
    int t = blockIdx.x;
    int b = t / (NBLKS * 18);
    int rem = t % (NBLKS * 18);
    int n = rem / 18;
    int r = NFT + rem % 18;
    int s = n * BLK + r;
    int c = threadIdx.x * 4;
    size_t row = (size_t)(b * SEQ + s);
    *(uint2*)(out + row * WIDTH + c) =
        *(const uint2*)(qkv + row * (3 * WIDTH) + 2 * WIDTH + c);
}

// ---------------- gather frame rows for head (to fp16) ----------------
__global__ void k_gather(const float* __restrict__ h, __half* __restrict__ g) {
    int m = blockIdx.x;
    int b = m / (NBLKS * NFT);
    int t = m % (NBLKS * NFT);
    int n = t / NFT, r = t % NFT;
    int s = n * BLK + r;
    int c = threadIdx.x * 4;
    float4 v = *(const float4*)(h + ((size_t)(b * SEQ + s)) * WIDTH + c);
    uint2 u;
    u.x = h2bits(v.x, v.y); u.y = h2bits(v.z, v.w);
    *(uint2*)(g + (size_t)m * WIDTH + c) = u;
}

// ---------------- launch ----------------
extern "C" void kernel_launch(void* const* d_in, const int* in_sizes, int n_in,
                              void* d_out, int out_size) {
    const float* x     = (const float*)d_in[0];
    const float* f     = (const float*)d_in[1];
    const float* delim = (const float*)d_in[2];
    const float* ln1s  = (const float*)d_in[3];
    const float* ln1b  = (const float*)d_in[4];
    const float* wqkv  = (const float*)d_in[5];
    const float* bqkv  = (const float*)d_in[6];
    const float* wo    = (const float*)d_in[7];
    const float* bo    = (const float*)d_in[8];
    const float* ln2s  = (const float*)d_in[9];
    const float* ln2b  = (const float*)d_in[10];
    const float* wfc   = (const float*)d_in[11];
    const float* bfc   = (const float*)d_in[12];
    const float* wpr   = (const float*)d_in[13];
    const float* bpr   = (const float*)d_in[14];
    const float* whead = (const float*)d_in[15];
    float* out = (float*)d_out;

    float *h;
    __half *a, *qkv, *attn, *mid, *w;
    cudaGetSymbolAddress((void**)&h,    g_h);
    cudaGetSymbolAddress((void**)&a,    g_a);
    cudaGetSymbolAddress((void**)&qkv,  g_qkv);
    cudaGetSymbolAddress((void**)&attn, g_attn);
    cudaGetSymbolAddress((void**)&mid,  g_mid);
    cudaGetSymbolAddress((void**)&w,    g_w);

    cudaFuncSetAttribute(k_mma<0>, cudaFuncAttributeMaxDynamicSharedMemorySize, GS_BYTES);
    cudaFuncSetAttribute(k_mma<1>, cudaFuncAttributeMaxDynamicSharedMemorySize, GS_BYTES);
    cudaFuncSetAttribute(k_mma<2>, cudaFuncAttributeMaxDynamicSharedMemorySize, GS_BYTES);
    cudaFuncSetAttribute(k_mma<3>, cudaFuncAttributeMaxDynamicSharedMemorySize, GS_BYTES);
    cudaFuncSetAttribute(k_mma<4>, cudaFuncAttributeMaxDynamicSharedMemorySize, GS_BYTES);

    // launch 0: weight conversion (single kernel)
    k_tohalf_all<<<(4849664 + 255) / 256, 256>>>(wqkv, wo, wfc, wpr, whead, w);
    // launch 1
    k_assemble<<<ROWS, 128>>>(x, f, delim, h);

    for (int l = 0; l < LAYERS; l++) {
        k_ln<<<ROWS, 128>>>(h, a, ln1s + l * WIDTH, ln1b + l * WIDTH);
        k_mma<4><<<dim3(MTILES, 12), 256, GS_BYTES>>>(
            a, w + WQ_OFF + (size_t)l * 3*WIDTH*WIDTH, bqkv + (size_t)l * 3*WIDTH,
            qkv, ROWS, 3*WIDTH, WIDTH);
        k_fattn<<<dim3(BATCH * NBLKS, HEADS), 128>>>(qkv, attn);
        k_copyv<<<BATCH * NBLKS * 18, 128>>>(qkv, attn);
        k_mma<2><<<dim3(MTILES, 4), 256, GS_BYTES>>>(
            attn, w + WO_OFF + (size_t)l * WIDTH*WIDTH, bo + (size_t)l * WIDTH,
            h, ROWS, WIDTH, WIDTH);
        k_ln<<<ROWS, 128>>>(h, a, ln2s + l * WIDTH, ln2b + l * WIDTH);
        k_mma<1><<<dim3(MTILES, 16), 256, GS_BYTES>>>(
            a, w + WF_OFF + (size_t)l * 4*WIDTH*WIDTH, bfc + (size_t)l * 4*WIDTH,
            mid, ROWS, 4*WIDTH, WIDTH);
        k_mma<2><<<dim3(MTILES, 4), 256, GS_BYTES>>>(
            mid, w + WP_OFF + (size_t)l * WIDTH*4*WIDTH, bpr + (size_t)l * WIDTH,
            h, ROWS, WIDTH, 4*WIDTH);
    }

    k_gather<<<BATCH * NBLKS * NFT, 128>>>(h, a);
    k_mma<3><<<dim3(48, 8), 256, GS_BYTES>>>(
        a, w + WH_OFF, nullptr, out, BATCH * NBLKS * NFT, 1024, WIDTH);
}